// round 1
// baseline (speedup 1.0000x reference)
#include <cuda_runtime.h>
#include <math.h>

#define BATCH   64
#define TOK     49
#define DIMSZ   768
#define NHEAD   12
#define DHEAD   64
#define FFSZ    3072
#define DEPTH   12
#define MTOK    (BATCH*TOK)     // 3136
#define LTOK    197

// ---------------- scratch (device globals: allocation-guard legal) ----------
__device__ float g_x  [MTOK*DIMSZ];
__device__ float g_h  [MTOK*DIMSZ];
__device__ float g_qkv[MTOK*3*DIMSZ];
__device__ float g_att[MTOK*DIMSZ];
__device__ float g_ff [MTOK*FFSZ];

// ---------------- patch embed: conv for the 49 selected tokens only ---------
__global__ void patch_embed_kernel(const float* __restrict__ inp,
                                   const float* __restrict__ conv_w,
                                   const float* __restrict__ ct,
                                   const float* __restrict__ pe,
                                   const int*   __restrict__ mask_idx)
{
    int blk = blockIdx.x;          // b*TOK + t
    int b = blk / TOK;
    int t = blk % TOK;
    int tid = threadIdx.x;         // 256

    int idx = mask_idx[t];
    idx = min(max(idx, 0), LTOK - 1);     // JAX clamps OOB gather (197 -> 196)

    float* outp = g_x + (size_t)blk * DIMSZ;

    if (idx == 0) {   // class token (never hit for this mask, but correct anyway)
        for (int d = tid; d < DIMSZ; d += 256)
            outp[d] = ct[d] + pe[d];
        return;
    }

    int p  = idx - 1;
    int ph = p / 14, pw = p % 14;

    __shared__ float ps[768];       // 16*16*3 patch pixels, k = (i*16+j)*3+c
    const float* base = inp + (((size_t)b * 224 + (size_t)ph * 16) * 224 + (size_t)pw * 16) * 3;
    for (int k = tid; k < 768; k += 256) {
        int ij = k / 3, c = k % 3;
        int i = ij / 16, j = ij % 16;
        ps[k] = base[((size_t)i * 224 + j) * 3 + c];
    }
    __syncthreads();

    float a0 = 0.f, a1 = 0.f, a2 = 0.f;
    #pragma unroll 4
    for (int k = 0; k < 768; k++) {
        float pv = ps[k];
        const float* w = conv_w + (size_t)k * DIMSZ;
        a0 += pv * w[tid];
        a1 += pv * w[tid + 256];
        a2 += pv * w[tid + 512];
    }
    const float* per = pe + (size_t)idx * DIMSZ;
    outp[tid]       = a0 + per[tid];
    outp[tid + 256] = a1 + per[tid + 256];
    outp[tid + 512] = a2 + per[tid + 512];
}

// ---------------- layernorm: one block per row ------------------------------
__global__ void layernorm_kernel(const float* __restrict__ x,
                                 const float* __restrict__ sc,
                                 const float* __restrict__ bi,
                                 float* __restrict__ out)
{
    int row = blockIdx.x;
    int tid = threadIdx.x;  // 256
    __shared__ float rs[DIMSZ];
    __shared__ float r1[8], r2[8];

    const float* xr = x + (size_t)row * DIMSZ;
    float s = 0.f, s2 = 0.f;
    for (int d = tid; d < DIMSZ; d += 256) {
        float v = xr[d];
        rs[d] = v;
        s += v; s2 += v * v;
    }
    #pragma unroll
    for (int o = 16; o; o >>= 1) {
        s  += __shfl_xor_sync(0xffffffffu, s,  o);
        s2 += __shfl_xor_sync(0xffffffffu, s2, o);
    }
    if ((tid & 31) == 0) { r1[tid >> 5] = s; r2[tid >> 5] = s2; }
    __syncthreads();
    if (tid == 0) {
        float a = 0.f, bsum = 0.f;
        #pragma unroll
        for (int i = 0; i < 8; i++) { a += r1[i]; bsum += r2[i]; }
        float m = a / DIMSZ;
        float v = fmaxf(bsum / DIMSZ - m * m, 0.f);
        r1[0] = m;
        r2[0] = rsqrtf(v + 1e-9f);
    }
    __syncthreads();
    float m = r1[0], inv = r2[0];
    float* op = out + (size_t)row * DIMSZ;
    for (int d = tid; d < DIMSZ; d += 256)
        op[d] = (rs[d] - m) * inv * sc[d] + bi[d];
}

// ---------------- attention: one block per (batch, head) --------------------
__global__ void attention_kernel()
{
    int bh = blockIdx.x;
    int b = bh / NHEAD, h = bh % NHEAD;
    int tid = threadIdx.x;   // 64

    __shared__ float qs[TOK][DHEAD + 1];
    __shared__ float ks[TOK][DHEAD + 1];
    __shared__ float vs[TOK][DHEAD + 1];

    for (int e = tid; e < TOK * DHEAD; e += 64) {
        int t = e / DHEAD, d = e % DHEAD;
        size_t rb = (size_t)(b * TOK + t) * (3 * DIMSZ) + (size_t)h * DHEAD + d;
        qs[t][d] = g_qkv[rb];
        ks[t][d] = g_qkv[rb + DIMSZ];
        vs[t][d] = g_qkv[rb + 2 * DIMSZ];
    }
    __syncthreads();
    if (tid >= TOK) return;

    float s[TOK];
    float mx = -1e30f;
    #pragma unroll 1
    for (int j = 0; j < TOK; j++) {
        float acc = 0.f;
        #pragma unroll
        for (int d = 0; d < DHEAD; d++) acc += qs[tid][d] * ks[j][d];
        acc *= 0.125f;                 // 1/sqrt(64)
        s[j] = acc;
        mx = fmaxf(mx, acc);
    }
    float sum = 0.f;
    #pragma unroll 1
    for (int j = 0; j < TOK; j++) { float e = expf(s[j] - mx); s[j] = e; sum += e; }
    float inv = 1.f / sum;

    float* op = g_att + (size_t)(b * TOK + tid) * DIMSZ + (size_t)h * DHEAD;
    #pragma unroll 1
    for (int d = 0; d < DHEAD; d++) {
        float acc = 0.f;
        #pragma unroll
        for (int j = 0; j < TOK; j++) acc += s[j] * vs[j][d];
        op[d] = acc * inv;
    }
}

// ---------------- fp32 tiled GEMM with fused epilogues -----------------------
// C[M,N] = epi( A[M,K] @ W[K,N] )
// EPI 0: plain   1: +res   2: gelu(+bias)   3: +bias +res
__device__ __forceinline__ float gelu_tanh(float x) {
    float x3 = x * x * x;
    return 0.5f * x * (1.f + tanhf(0.7978845608028654f * (x + 0.044715f * x3)));
}

template<int EPI>
__global__ void gemm_kernel(const float* __restrict__ A,
                            const float* __restrict__ Wm,
                            const float* __restrict__ bias,
                            const float* __restrict__ res,
                            float* __restrict__ C,
                            int M, int N, int K)
{
    const int BM = 64, BN = 64, BK = 32;
    __shared__ float As[BK][BM];
    __shared__ float Bs[BK][BN];

    int tid = threadIdx.x;                 // 256
    int bm = blockIdx.y * BM;
    int bn = blockIdx.x * BN;
    int tm = (tid / 16) * 4;
    int tn = (tid % 16) * 4;

    float c[4][4] = {};

    int ar = tid / 8,  ac = (tid % 8) * 4;     // A load coords
    int br = tid / 16, bc = (tid % 16) * 4;    // B load coords

    for (int k0 = 0; k0 < K; k0 += BK) {
        #pragma unroll
        for (int rr = 0; rr < 2; rr++) {
            float4 v = *(const float4*)&A[(size_t)(bm + ar + rr * 32) * K + k0 + ac];
            As[ac + 0][ar + rr * 32] = v.x;
            As[ac + 1][ar + rr * 32] = v.y;
            As[ac + 2][ar + rr * 32] = v.z;
            As[ac + 3][ar + rr * 32] = v.w;
        }
        #pragma unroll
        for (int rr = 0; rr < 2; rr++) {
            float4 v = *(const float4*)&Wm[(size_t)(k0 + br + rr * 16) * N + bn + bc];
            *(float4*)&Bs[br + rr * 16][bc] = v;
        }
        __syncthreads();

        #pragma unroll
        for (int k = 0; k < BK; k++) {
            float4 a4 = *(const float4*)&As[k][tm];
            float4 b4 = *(const float4*)&Bs[k][tn];
            float av[4] = {a4.x, a4.y, a4.z, a4.w};
            float bw[4] = {b4.x, b4.y, b4.z, b4.w};
            #pragma unroll
            for (int i = 0; i < 4; i++)
                #pragma unroll
                for (int j = 0; j < 4; j++)
                    c[i][j] += av[i] * bw[j];
        }
        __syncthreads();
    }

    #pragma unroll
    for (int i = 0; i < 4; i++) {
        size_t row = (size_t)(bm + tm + i);
        #pragma unroll
        for (int j = 0; j < 4; j++) {
            int col = bn + tn + j;
            float v = c[i][j];
            if (EPI == 1)      v += res[row * N + col];
            else if (EPI == 2) v = gelu_tanh(v + bias[col]);
            else if (EPI == 3) v += bias[col] + res[row * N + col];
            C[row * N + col] = v;
        }
    }
}

// ---------------- launcher ---------------------------------------------------
extern "C" void kernel_launch(void* const* d_in, const int* in_sizes, int n_in,
                              void* d_out, int out_size)
{
    const float* inputs  = (const float*)d_in[0];
    const float* conv_w  = (const float*)d_in[1];
    const float* ct      = (const float*)d_in[2];
    const float* pe      = (const float*)d_in[3];
    const float* ln1_s   = (const float*)d_in[4];
    const float* ln1_b   = (const float*)d_in[5];
    const float* qkv_w   = (const float*)d_in[6];
    const float* proj_w  = (const float*)d_in[7];
    const float* ln2_s   = (const float*)d_in[8];
    const float* ln2_b   = (const float*)d_in[9];
    const float* w1      = (const float*)d_in[10];
    const float* b1      = (const float*)d_in[11];
    const float* w2      = (const float*)d_in[12];
    const float* b2      = (const float*)d_in[13];
    const int*   mask_idx= (const int*)  d_in[14];
    float* out = (float*)d_out;

    float *xbuf, *hbuf, *qkvbuf, *ffbuf, *attbuf;
    cudaGetSymbolAddress((void**)&xbuf,  g_x);
    cudaGetSymbolAddress((void**)&hbuf,  g_h);
    cudaGetSymbolAddress((void**)&qkvbuf,g_qkv);
    cudaGetSymbolAddress((void**)&attbuf,g_att);
    cudaGetSymbolAddress((void**)&ffbuf, g_ff);

    patch_embed_kernel<<<MTOK, 256>>>(inputs, conv_w, ct, pe, mask_idx);

    for (int l = 0; l < DEPTH; l++) {
        layernorm_kernel<<<MTOK, 256>>>(xbuf, ln1_s + (size_t)l * DIMSZ,
                                        ln1_b + (size_t)l * DIMSZ, hbuf);

        gemm_kernel<0><<<dim3(3 * DIMSZ / 64, MTOK / 64), 256>>>(
            hbuf, qkv_w + (size_t)l * DIMSZ * 3 * DIMSZ,
            nullptr, nullptr, qkvbuf, MTOK, 3 * DIMSZ, DIMSZ);

        attention_kernel<<<BATCH * NHEAD, 64>>>();

        gemm_kernel<1><<<dim3(DIMSZ / 64, MTOK / 64), 256>>>(
            attbuf, proj_w + (size_t)l * DIMSZ * DIMSZ,
            nullptr, xbuf, xbuf, MTOK, DIMSZ, DIMSZ);

        layernorm_kernel<<<MTOK, 256>>>(xbuf, ln2_s + (size_t)l * DIMSZ,
                                        ln2_b + (size_t)l * DIMSZ, hbuf);

        gemm_kernel<2><<<dim3(FFSZ / 64, MTOK / 64), 256>>>(
            hbuf, w1 + (size_t)l * DIMSZ * FFSZ,
            b1 + (size_t)l * FFSZ, nullptr, ffbuf, MTOK, FFSZ, DIMSZ);

        float* cdst = (l == DEPTH - 1) ? out : xbuf;
        gemm_kernel<3><<<dim3(DIMSZ / 64, MTOK / 64), 256>>>(
            ffbuf, w2 + (size_t)l * FFSZ * DIMSZ,
            b2 + (size_t)l * DIMSZ, xbuf, cdst, MTOK, DIMSZ, FFSZ);
    }
}

// round 3
// speedup vs baseline: 2.8453x; 2.8453x over previous
#include <cuda_runtime.h>
#include <cuda_bf16.h>
#include <cstdint>
#include <math.h>

#define BATCH   64
#define TOK     49
#define DIMSZ   768
#define NHEAD   12
#define DHEAD   64
#define FFSZ    3072
#define DEPTH   12
#define MTOK    (BATCH*TOK)     // 3136
#define MPAD    3200            // 25 tiles of 128

// ---------------- weight split offsets (elements) ----------------------------
#define OFF_CONV 0
#define SZ_CONV  (768*768)
#define OFF_QKV  (OFF_CONV + SZ_CONV)
#define SZ_QKV   (DEPTH*DIMSZ*3*DIMSZ)
#define OFF_PROJ (OFF_QKV + SZ_QKV)
#define SZ_PROJ  (DEPTH*DIMSZ*DIMSZ)
#define OFF_W1   (OFF_PROJ + SZ_PROJ)
#define SZ_W1    (DEPTH*DIMSZ*FFSZ)
#define OFF_W2   (OFF_W1 + SZ_W1)
#define SZ_W2    (DEPTH*FFSZ*DIMSZ)
#define WTOTAL   (OFF_W2 + SZ_W2)

// ---------------- scratch (device globals) ----------------------------------
__device__ float g_x  [MPAD*DIMSZ];                // residual stream (fp32)
__device__ float g_qkv[MPAD*3*DIMSZ];              // qkv (fp32)
__device__ __nv_bfloat16 g_hh [MPAD*DIMSZ];        // LN out hi/lo
__device__ __nv_bfloat16 g_hl [MPAD*DIMSZ];
__device__ __nv_bfloat16 g_ath[MPAD*DIMSZ];        // attention out / patches hi/lo
__device__ __nv_bfloat16 g_atl[MPAD*DIMSZ];
__device__ __nv_bfloat16 g_fh [MPAD*FFSZ];         // FF1 out hi/lo
__device__ __nv_bfloat16 g_fl [MPAD*FFSZ];
__device__ __nv_bfloat16 g_wh [WTOTAL];            // all weights hi
__device__ __nv_bfloat16 g_wl [WTOTAL];            // all weights lo

// ---------------- helpers ----------------------------------------------------
__device__ __forceinline__ uint32_t smem_u32(const void* p) {
    uint32_t a;
    asm("{ .reg .u64 t; cvta.to.shared.u64 t, %1; cvt.u32.u64 %0, t; }" : "=r"(a) : "l"(p));
    return a;
}
#define CP_ASYNC16(dst, src) \
    asm volatile("cp.async.cg.shared.global [%0], [%1], 16;" :: "r"(dst), "l"(src))
#define CP_COMMIT() asm volatile("cp.async.commit_group;" ::: "memory")
#define CP_WAIT1()  asm volatile("cp.async.wait_group 1;" ::: "memory")
#define CP_WAIT0()  asm volatile("cp.async.wait_group 0;" ::: "memory")

__device__ __forceinline__ void ldmx4(uint32_t& r0, uint32_t& r1, uint32_t& r2, uint32_t& r3,
                                      uint32_t addr) {
    asm volatile("ldmatrix.sync.aligned.m8n8.x4.shared.b16 {%0,%1,%2,%3}, [%4];"
                 : "=r"(r0), "=r"(r1), "=r"(r2), "=r"(r3) : "r"(addr));
}
__device__ __forceinline__ void ldmx4t(uint32_t& r0, uint32_t& r1, uint32_t& r2, uint32_t& r3,
                                       uint32_t addr) {
    asm volatile("ldmatrix.sync.aligned.m8n8.x4.trans.shared.b16 {%0,%1,%2,%3}, [%4];"
                 : "=r"(r0), "=r"(r1), "=r"(r2), "=r"(r3) : "r"(addr));
}
__device__ __forceinline__ void mma16816(float* c, const uint32_t* a, uint32_t b0, uint32_t b1) {
    asm volatile("mma.sync.aligned.m16n8k16.row.col.f32.bf16.bf16.f32 "
                 "{%0,%1,%2,%3},{%4,%5,%6,%7},{%8,%9},{%0,%1,%2,%3};"
                 : "+f"(c[0]), "+f"(c[1]), "+f"(c[2]), "+f"(c[3])
                 : "r"(a[0]), "r"(a[1]), "r"(a[2]), "r"(a[3]), "r"(b0), "r"(b1));
}

__device__ __forceinline__ void split1(float x, __nv_bfloat16& h, __nv_bfloat16& l) {
    h = __float2bfloat16(x);
    l = __float2bfloat16(x - __bfloat162float(h));
}
__device__ __forceinline__ float gelu_tanh(float x) {
    float x3 = x * x * x;
    return 0.5f * x * (1.f + tanhf(0.7978845608028654f * (x + 0.044715f * x3)));
}

// ---------------- weight split kernel ----------------------------------------
__global__ void split_kernel(const float* __restrict__ src,
                             __nv_bfloat16* __restrict__ hi,
                             __nv_bfloat16* __restrict__ lo, int n)
{
    int i = (blockIdx.x * 256 + threadIdx.x) * 4;
    if (i >= n) return;
    float4 v = *(const float4*)(src + i);
    __nv_bfloat16 h, l;
    split1(v.x, h, l); hi[i]   = h; lo[i]   = l;
    split1(v.y, h, l); hi[i+1] = h; lo[i+1] = l;
    split1(v.z, h, l); hi[i+2] = h; lo[i+2] = l;
    split1(v.w, h, l); hi[i+3] = h; lo[i+3] = l;
}

// ---------------- mma GEMM: C[M,N] = epi(A[M,K] @ W[K,N]) --------------------
// A,W given as bf16 hi/lo pairs (3-term fp32 emulation).
// EPI 0: plain f32   1: +res f32   2: gelu(+bias) -> bf16 hi/lo   3: +bias+res f32
#define BK       32
#define ASTRIDE  80         // bytes per A smem row (64 used + pad)
#define BSTRIDE  272        // bytes per B smem row (256 used + pad)
#define A_TILE   (128*ASTRIDE)          // 10240
#define B_TILE   (BK*BSTRIDE)           // 8704
#define STAGE_SZ (2*A_TILE + 2*B_TILE)  // 37888
#define SMEM_GEMM (2*STAGE_SZ)          // 75776

template<int EPI>
__global__ void __launch_bounds__(256, 2)
gemm_mma(const __nv_bfloat16* __restrict__ Ah, const __nv_bfloat16* __restrict__ Al,
         const __nv_bfloat16* __restrict__ Wh, const __nv_bfloat16* __restrict__ Wl,
         const float* __restrict__ bias, const float* __restrict__ res,
         float* __restrict__ C,
         __nv_bfloat16* __restrict__ Chi, __nv_bfloat16* __restrict__ Clo,
         int Mw, int N, int K)
{
    extern __shared__ char smem[];
    uint32_t sb = smem_u32(smem);
    int tid = threadIdx.x, lane = tid & 31, wid = tid >> 5;
    int m0 = blockIdx.y * 128, n0 = blockIdx.x * 128;
    int warpM = (wid & 3) * 32, warpN = (wid >> 2) * 64;

    // global source coords for cp.async
    int arow = tid >> 1, acol = (tid & 1) * 16;   // A: 128 rows x 32 k, 16 elems/thr
    int brow = tid >> 3, bcol = (tid & 7) * 16;   // B: 32 rows x 128 n
    const __nv_bfloat16* gAh = Ah + (size_t)(m0 + arow) * K + acol;
    const __nv_bfloat16* gAl = Al + (size_t)(m0 + arow) * K + acol;
    const __nv_bfloat16* gBh = Wh + (size_t)brow * N + n0 + bcol;
    const __nv_bfloat16* gBl = Wl + (size_t)brow * N + n0 + bcol;
    uint32_t sAoff = (uint32_t)arow * ASTRIDE + (uint32_t)acol * 2;
    uint32_t sBoff = (uint32_t)brow * BSTRIDE + (uint32_t)bcol * 2;

    const int nch = K >> 5;

    auto issue = [&](int chunk, int buf) {
        uint32_t st = sb + (uint32_t)buf * STAGE_SZ;
        const __nv_bfloat16* pAh = gAh + chunk * BK;
        const __nv_bfloat16* pAl = gAl + chunk * BK;
        const __nv_bfloat16* pBh = gBh + (size_t)chunk * BK * N;
        const __nv_bfloat16* pBl = gBl + (size_t)chunk * BK * N;
        CP_ASYNC16(st + sAoff,                   pAh);
        CP_ASYNC16(st + sAoff + 16,              pAh + 8);
        CP_ASYNC16(st + A_TILE + sAoff,          pAl);
        CP_ASYNC16(st + A_TILE + sAoff + 16,     pAl + 8);
        CP_ASYNC16(st + 2*A_TILE + sBoff,        pBh);
        CP_ASYNC16(st + 2*A_TILE + sBoff + 16,   pBh + 8);
        CP_ASYNC16(st + 2*A_TILE + B_TILE + sBoff,      pBl);
        CP_ASYNC16(st + 2*A_TILE + B_TILE + sBoff + 16, pBl + 8);
    };

    issue(0, 0); CP_COMMIT();
    issue(1, 1); CP_COMMIT();          // nch >= 24 always

    float acc[2][8][4] = {};

    for (int i = 0; i < nch; i++) {
        if (i + 1 < nch) { CP_WAIT1(); } else { CP_WAIT0(); }
        __syncthreads();
        uint32_t st = sb + (uint32_t)(i & 1) * STAGE_SZ;

        #pragma unroll
        for (int kk = 0; kk < 2; kk++) {
            uint32_t aAddr = st + (uint32_t)(warpM + (lane & 15)) * ASTRIDE
                               + (uint32_t)kk * 32 + (uint32_t)(lane >> 4) * 16;
            uint32_t ah[2][4], al[2][4];
            ldmx4(ah[0][0], ah[0][1], ah[0][2], ah[0][3], aAddr);
            ldmx4(ah[1][0], ah[1][1], ah[1][2], ah[1][3], aAddr + 16*ASTRIDE);
            ldmx4(al[0][0], al[0][1], al[0][2], al[0][3], aAddr + A_TILE);
            ldmx4(al[1][0], al[1][1], al[1][2], al[1][3], aAddr + A_TILE + 16*ASTRIDE);

            #pragma unroll
            for (int nt = 0; nt < 4; nt++) {
                uint32_t bAddr = st + 2*A_TILE
                    + (uint32_t)(kk*16 + (lane & 15)) * BSTRIDE
                    + (uint32_t)(warpN + nt*16 + (lane >> 4)*8) * 2;
                uint32_t bh[4], bl[4];
                ldmx4t(bh[0], bh[1], bh[2], bh[3], bAddr);
                ldmx4t(bl[0], bl[1], bl[2], bl[3], bAddr + B_TILE);
                #pragma unroll
                for (int mt = 0; mt < 2; mt++) {
                    mma16816(acc[mt][2*nt+0], ah[mt], bh[0], bh[1]);
                    mma16816(acc[mt][2*nt+1], ah[mt], bh[2], bh[3]);
                    mma16816(acc[mt][2*nt+0], ah[mt], bl[0], bl[1]);
                    mma16816(acc[mt][2*nt+1], ah[mt], bl[2], bl[3]);
                    mma16816(acc[mt][2*nt+0], al[mt], bh[0], bh[1]);
                    mma16816(acc[mt][2*nt+1], al[mt], bh[2], bh[3]);
                }
            }
        }
        __syncthreads();
        if (i + 2 < nch) { issue(i + 2, i & 1); CP_COMMIT(); }
    }

    // ---- epilogue: registers -> global ----
    int r_ = lane >> 2, c_ = (lane & 3) * 2;
    #pragma unroll
    for (int mt = 0; mt < 2; mt++) {
        #pragma unroll
        for (int nt8 = 0; nt8 < 8; nt8++) {
            int row0 = m0 + warpM + mt*16 + r_;
            int col  = n0 + warpN + nt8*8 + c_;
            #pragma unroll
            for (int half = 0; half < 2; half++) {
                int row = row0 + half*8;
                if (row >= Mw) continue;
                float v0 = acc[mt][nt8][half*2 + 0];
                float v1 = acc[mt][nt8][half*2 + 1];
                size_t base = (size_t)row * N + col;
                if (EPI == 0) {
                    *(float2*)(C + base) = make_float2(v0, v1);
                } else if (EPI == 1) {
                    float2 r2 = *(const float2*)(res + base);
                    *(float2*)(C + base) = make_float2(v0 + r2.x, v1 + r2.y);
                } else if (EPI == 2) {
                    v0 = gelu_tanh(v0 + bias[col]);
                    v1 = gelu_tanh(v1 + bias[col + 1]);
                    __nv_bfloat16 h0, l0, h1, l1;
                    split1(v0, h0, l0); split1(v1, h1, l1);
                    __nv_bfloat162 hv; hv.x = h0; hv.y = h1;
                    __nv_bfloat162 lv; lv.x = l0; lv.y = l1;
                    *(__nv_bfloat162*)(Chi + base) = hv;
                    *(__nv_bfloat162*)(Clo + base) = lv;
                } else {
                    float2 r2 = *(const float2*)(res + base);
                    *(float2*)(C + base) = make_float2(v0 + bias[col] + r2.x,
                                                       v1 + bias[col+1] + r2.y);
                }
            }
        }
    }
}

// ---------------- patch gather -> bf16 hi/lo ---------------------------------
__global__ void gather_patches_kernel(const float* __restrict__ inp,
                                      const int* __restrict__ mask_idx)
{
    int blk = blockIdx.x;
    int b = blk / TOK, t = blk % TOK;
    int tid = threadIdx.x;
    int idx = min(max(mask_idx[t], 1), 196);
    int p = idx - 1;
    int ph = p / 14, pw = p % 14;
    const float* base = inp + (((size_t)b * 224 + (size_t)ph * 16) * 224 + (size_t)pw * 16) * 3;
    size_t ob = (size_t)blk * DIMSZ;
    for (int k = tid; k < 768; k += 256) {
        int ij = k / 3, c = k % 3;
        int i = ij / 16, j = ij % 16;
        float v = base[((size_t)i * 224 + j) * 3 + c];
        __nv_bfloat16 h, l;
        split1(v, h, l);
        g_ath[ob + k] = h;
        g_atl[ob + k] = l;
    }
}

__global__ void add_pe_kernel(const float* __restrict__ pe,
                              const int* __restrict__ mask_idx)
{
    int row = blockIdx.x;
    int t = row % TOK;
    int tid = threadIdx.x;
    int idx = min(max(mask_idx[t], 0), 196);
    const float* per = pe + (size_t)idx * DIMSZ;
    float* xp = g_x + (size_t)row * DIMSZ;
    for (int d = tid; d < DIMSZ; d += 256)
        xp[d] += per[d];
}

// ---------------- layernorm: fp32 in -> bf16 hi/lo out -----------------------
__global__ void layernorm_kernel(const float* __restrict__ x,
                                 const float* __restrict__ sc,
                                 const float* __restrict__ bi,
                                 __nv_bfloat16* __restrict__ oh,
                                 __nv_bfloat16* __restrict__ ol)
{
    int row = blockIdx.x;
    int tid = threadIdx.x;  // 256
    __shared__ float rs[DIMSZ];
    __shared__ float r1[8], r2[8];

    const float* xr = x + (size_t)row * DIMSZ;
    float s = 0.f, s2 = 0.f;
    for (int d = tid; d < DIMSZ; d += 256) {
        float v = xr[d];
        rs[d] = v;
        s += v; s2 += v * v;
    }
    #pragma unroll
    for (int o = 16; o; o >>= 1) {
        s  += __shfl_xor_sync(0xffffffffu, s,  o);
        s2 += __shfl_xor_sync(0xffffffffu, s2, o);
    }
    if ((tid & 31) == 0) { r1[tid >> 5] = s; r2[tid >> 5] = s2; }
    __syncthreads();
    if (tid == 0) {
        float a = 0.f, bsum = 0.f;
        #pragma unroll
        for (int i = 0; i < 8; i++) { a += r1[i]; bsum += r2[i]; }
        float m = a / DIMSZ;
        float v = fmaxf(bsum / DIMSZ - m * m, 0.f);
        r1[0] = m;
        r2[0] = rsqrtf(v + 1e-9f);
    }
    __syncthreads();
    float m = r1[0], inv = r2[0];
    size_t ob = (size_t)row * DIMSZ;
    for (int d = tid; d < DIMSZ; d += 256) {
        float v = (rs[d] - m) * inv * sc[d] + bi[d];
        __nv_bfloat16 h, l;
        split1(v, h, l);
        oh[ob + d] = h;
        ol[ob + d] = l;
    }
}

// ---------------- attention: block per (b,h) ---------------------------------
__global__ void __launch_bounds__(256, 4) attention_kernel()
{
    int bh = blockIdx.x;
    int b = bh / NHEAD, h = bh % NHEAD;
    int tid = threadIdx.x;
    int wid = tid >> 5, lid = tid & 31;

    __shared__ float qs[TOK][DHEAD + 1];
    __shared__ float ks[TOK][DHEAD + 1];
    __shared__ float vs[TOK][DHEAD + 1];
    __shared__ float ps[TOK][TOK + 1];

    for (int e = tid; e < TOK * DHEAD; e += 256) {
        int t = e / DHEAD, d = e % DHEAD;
        size_t rb = (size_t)(b * TOK + t) * (3 * DIMSZ) + (size_t)h * DHEAD + d;
        qs[t][d] = g_qkv[rb];
        ks[t][d] = g_qkv[rb + DIMSZ];
        vs[t][d] = g_qkv[rb + 2 * DIMSZ];
    }
    __syncthreads();

    for (int e = tid; e < TOK * TOK; e += 256) {
        int q = e / TOK, j = e % TOK;
        float acc = 0.f;
        #pragma unroll
        for (int d = 0; d < DHEAD; d++) acc += qs[q][d] * ks[j][d];
        ps[q][j] = acc * 0.125f;
    }
    __syncthreads();

    for (int row = wid; row < TOK; row += 8) {
        float mx = -1e30f;
        for (int j = lid; j < TOK; j += 32) mx = fmaxf(mx, ps[row][j]);
        #pragma unroll
        for (int o = 16; o; o >>= 1) mx = fmaxf(mx, __shfl_xor_sync(0xffffffffu, mx, o));
        float sum = 0.f, e0 = 0.f, e1 = 0.f;
        if (lid < TOK)      { e0 = expf(ps[row][lid] - mx);      sum += e0; }
        if (lid + 32 < TOK) { e1 = expf(ps[row][lid + 32] - mx); sum += e1; }
        #pragma unroll
        for (int o = 16; o; o >>= 1) sum += __shfl_xor_sync(0xffffffffu, sum, o);
        float inv = 1.f / sum;
        if (lid < TOK)      ps[row][lid]      = e0 * inv;
        if (lid + 32 < TOK) ps[row][lid + 32] = e1 * inv;
    }
    __syncthreads();

    for (int e = tid; e < TOK * DHEAD; e += 256) {
        int q = e / DHEAD, d = e % DHEAD;
        float acc = 0.f;
        #pragma unroll
        for (int j = 0; j < TOK; j++) acc += ps[q][j] * vs[j][d];
        size_t ob = (size_t)(b * TOK + q) * DIMSZ + (size_t)h * DHEAD + d;
        __nv_bfloat16 hi, lo;
        split1(acc, hi, lo);
        g_ath[ob] = hi;
        g_atl[ob] = lo;
    }
}

// ---------------- launcher ---------------------------------------------------
static void launch_gemm(int epi, const __nv_bfloat16* Ah, const __nv_bfloat16* Al,
                        const __nv_bfloat16* Wh, const __nv_bfloat16* Wl,
                        const float* bias, const float* res,
                        float* C, __nv_bfloat16* Chi, __nv_bfloat16* Clo,
                        int Mw, int N, int K)
{
    dim3 grid(N / 128, MPAD / 128);
    switch (epi) {
    case 0: gemm_mma<0><<<grid, 256, SMEM_GEMM>>>(Ah, Al, Wh, Wl, bias, res, C, Chi, Clo, Mw, N, K); break;
    case 1: gemm_mma<1><<<grid, 256, SMEM_GEMM>>>(Ah, Al, Wh, Wl, bias, res, C, Chi, Clo, Mw, N, K); break;
    case 2: gemm_mma<2><<<grid, 256, SMEM_GEMM>>>(Ah, Al, Wh, Wl, bias, res, C, Chi, Clo, Mw, N, K); break;
    default: gemm_mma<3><<<grid, 256, SMEM_GEMM>>>(Ah, Al, Wh, Wl, bias, res, C, Chi, Clo, Mw, N, K); break;
    }
}

extern "C" void kernel_launch(void* const* d_in, const int* in_sizes, int n_in,
                              void* d_out, int out_size)
{
    const float* inputs  = (const float*)d_in[0];
    const float* conv_w  = (const float*)d_in[1];
    const float* pe      = (const float*)d_in[3];
    const float* ln1_s   = (const float*)d_in[4];
    const float* ln1_b   = (const float*)d_in[5];
    const float* qkv_w   = (const float*)d_in[6];
    const float* proj_w  = (const float*)d_in[7];
    const float* ln2_s   = (const float*)d_in[8];
    const float* ln2_b   = (const float*)d_in[9];
    const float* w1      = (const float*)d_in[10];
    const float* b1      = (const float*)d_in[11];
    const float* w2      = (const float*)d_in[12];
    const float* b2      = (const float*)d_in[13];
    const int*   mask_idx= (const int*)  d_in[14];
    float* out = (float*)d_out;

    cudaFuncSetAttribute(gemm_mma<0>, cudaFuncAttributeMaxDynamicSharedMemorySize, SMEM_GEMM);
    cudaFuncSetAttribute(gemm_mma<1>, cudaFuncAttributeMaxDynamicSharedMemorySize, SMEM_GEMM);
    cudaFuncSetAttribute(gemm_mma<2>, cudaFuncAttributeMaxDynamicSharedMemorySize, SMEM_GEMM);
    cudaFuncSetAttribute(gemm_mma<3>, cudaFuncAttributeMaxDynamicSharedMemorySize, SMEM_GEMM);

    float *xbuf, *qkvbuf;
    __nv_bfloat16 *hh, *hl, *ath, *atl, *fh, *fl, *wh, *wl;
    cudaGetSymbolAddress((void**)&xbuf,  g_x);
    cudaGetSymbolAddress((void**)&qkvbuf,g_qkv);
    cudaGetSymbolAddress((void**)&hh,  g_hh);
    cudaGetSymbolAddress((void**)&hl,  g_hl);
    cudaGetSymbolAddress((void**)&ath, g_ath);
    cudaGetSymbolAddress((void**)&atl, g_atl);
    cudaGetSymbolAddress((void**)&fh,  g_fh);
    cudaGetSymbolAddress((void**)&fl,  g_fl);
    cudaGetSymbolAddress((void**)&wh,  g_wh);
    cudaGetSymbolAddress((void**)&wl,  g_wl);

    // ---- split all weights once per call ----
    split_kernel<<<(SZ_CONV/4 + 255)/256, 256>>>(conv_w, wh + OFF_CONV, wl + OFF_CONV, SZ_CONV);
    split_kernel<<<(SZ_QKV /4 + 255)/256, 256>>>(qkv_w,  wh + OFF_QKV,  wl + OFF_QKV,  SZ_QKV);
    split_kernel<<<(SZ_PROJ/4 + 255)/256, 256>>>(proj_w, wh + OFF_PROJ, wl + OFF_PROJ, SZ_PROJ);
    split_kernel<<<(SZ_W1  /4 + 255)/256, 256>>>(w1,     wh + OFF_W1,   wl + OFF_W1,   SZ_W1);
    split_kernel<<<(SZ_W2  /4 + 255)/256, 256>>>(w2,     wh + OFF_W2,   wl + OFF_W2,   SZ_W2);

    // ---- patch embed = gather -> GEMM -> +pe ----
    gather_patches_kernel<<<MTOK, 256>>>(inputs, mask_idx);
    launch_gemm(0, ath, atl, wh + OFF_CONV, wl + OFF_CONV,
                nullptr, nullptr, xbuf, nullptr, nullptr, MPAD, DIMSZ, DIMSZ);
    add_pe_kernel<<<MTOK, 256>>>(pe, mask_idx);

    for (int l = 0; l < DEPTH; l++) {
        layernorm_kernel<<<MTOK, 256>>>(xbuf, ln1_s + (size_t)l * DIMSZ,
                                        ln1_b + (size_t)l * DIMSZ, hh, hl);

        launch_gemm(0, hh, hl,
                    wh + OFF_QKV + (size_t)l * DIMSZ * 3 * DIMSZ,
                    wl + OFF_QKV + (size_t)l * DIMSZ * 3 * DIMSZ,
                    nullptr, nullptr, qkvbuf, nullptr, nullptr, MPAD, 3 * DIMSZ, DIMSZ);

        attention_kernel<<<BATCH * NHEAD, 256>>>();

        launch_gemm(1, ath, atl,
                    wh + OFF_PROJ + (size_t)l * DIMSZ * DIMSZ,
                    wl + OFF_PROJ + (size_t)l * DIMSZ * DIMSZ,
                    nullptr, xbuf, xbuf, nullptr, nullptr, MPAD, DIMSZ, DIMSZ);

        layernorm_kernel<<<MTOK, 256>>>(xbuf, ln2_s + (size_t)l * DIMSZ,
                                        ln2_b + (size_t)l * DIMSZ, hh, hl);

        launch_gemm(2, hh, hl,
                    wh + OFF_W1 + (size_t)l * DIMSZ * FFSZ,
                    wl + OFF_W1 + (size_t)l * DIMSZ * FFSZ,
                    b1 + (size_t)l * FFSZ, nullptr, nullptr, fh, fl, MPAD, FFSZ, DIMSZ);

        if (l == DEPTH - 1) {
            launch_gemm(3, fh, fl,
                        wh + OFF_W2 + (size_t)l * FFSZ * DIMSZ,
                        wl + OFF_W2 + (size_t)l * FFSZ * DIMSZ,
                        b2 + (size_t)l * DIMSZ, xbuf, out, nullptr, nullptr, MTOK, DIMSZ, FFSZ);
        } else {
            launch_gemm(3, fh, fl,
                        wh + OFF_W2 + (size_t)l * FFSZ * DIMSZ,
                        wl + OFF_W2 + (size_t)l * FFSZ * DIMSZ,
                        b2 + (size_t)l * DIMSZ, xbuf, xbuf, nullptr, nullptr, MPAD, DIMSZ, FFSZ);
        }
    }
}